// round 1
// baseline (speedup 1.0000x reference)
#include <cuda_runtime.h>

// Problem constants
#define B_ 4
#define H_ 192
#define W_ 640
#define C_ 32
#define S_ 32

struct __align__(16) Tab { float w0, w1; int i0, i1; };

// Precomputed per-(b,s,w) and per-(b,s,h) bilinear tables (allocation-free scratch)
__device__ Tab d_wtab[B_ * S_ * W_];
__device__ Tab d_htab[B_ * S_ * H_];

// ---------------------------------------------------------------------------
// Table build: for each (b,s,pos) compute sample coord, weights (with border
// masks folded in) and clamped indices. Matches reference math exactly:
//   D = (d==0) ? 0 : 1/(1/d + tz); alpha = 1 - D*tz
//   beta  = D*tz*ox + D*fx*Tx   (w axis)
//   gamma = D*tz*oy + D*fy*Ty   (h axis)
// ---------------------------------------------------------------------------
__global__ void build_tables(const float* __restrict__ origin,
                             const float* __restrict__ focal,
                             const float* __restrict__ T12)
{
    int idx = blockIdx.x * blockDim.x + threadIdx.x;
    const int totalW = B_ * S_ * W_;
    const int totalH = B_ * S_ * H_;
    if (idx >= totalW + totalH) return;

    bool isW = idx < totalW;
    int rem  = isW ? idx : idx - totalW;
    int N    = isW ? W_ : H_;
    int pos  = rem % N;
    int s    = (rem / N) % S_;
    int b    = rem / (N * S_);

    float tz = T12[b * 3 + 2];
    float d  = (float)s;
    float D  = (s == 0) ? 0.0f : 1.0f / (1.0f / d + tz);
    float alpha = 1.0f - D * tz;

    float off;
    if (isW) off = D * tz * origin[b * 2 + 0] + D * focal[b * 2 + 0] * T12[b * 3 + 0];
    else     off = D * tz * origin[b * 2 + 1] + D * focal[b * 2 + 1] * T12[b * 3 + 1];

    float sp = alpha * (float)pos + off;
    float f0 = floorf(sp);
    float fr = sp - f0;
    int i0 = (int)f0;
    int i1 = i0 + 1;

    Tab t;
    t.w0 = (i0 >= 0 && i0 < N) ? (1.0f - fr) : 0.0f;
    t.w1 = (i1 >= 0 && i1 < N) ? fr          : 0.0f;
    t.i0 = min(max(i0, 0), N - 1);
    t.i1 = min(max(i1, 0), N - 1);

    if (isW) d_wtab[(b * S_ + s) * W_ + pos] = t;
    else     d_htab[(b * S_ + s) * H_ + pos] = t;
}

// ---------------------------------------------------------------------------
// Main kernel.
// Block = 256 threads = 8 warps, covering an 8(w) x 4(h) pixel tile.
// Warp = 4 adjacent-w pixels; lane layout: sub = lane>>3 (pixel), cg = lane&7
// (channel group of 4 -> float4). Per step: 4 coalesced float4 tap loads per
// pixel, bilinear + dot, 3-shuffle reduce over the 8 channel lanes, scalar
// parked in smem; final coalesced float4 store (S is innermost in output).
// ---------------------------------------------------------------------------
__global__ __launch_bounds__(256) void corr_kernel(
    const float4* __restrict__ x4,
    const float4* __restrict__ y4,
    float4* __restrict__ out4)
{
    const int tid  = threadIdx.x;
    const int wi   = tid >> 5;
    const int lane = tid & 31;
    const int sub  = lane >> 3;
    const int cg   = lane & 7;

    // Block tile decode: grid = (W/8) * (H/4) * B blocks
    int bx  = blockIdx.x;
    int twi = bx % (W_ / 8);
    int thi = (bx / (W_ / 8)) % (H_ / 4);
    int b   = bx / ((W_ / 8) * (H_ / 4));

    int w = twi * 8 + (wi & 1) * 4 + sub;
    int h = thi * 4 + (wi >> 1);

    int p = (b * H_ + h) * W_ + w;   // linear pixel index

    // y vector for this pixel's channel group, pre-scaled by 1/C
    float4 yv = y4[p * (C_ / 4) + cg];
    const float sc = 1.0f / (float)C_;
    yv.x *= sc; yv.y *= sc; yv.z *= sc; yv.w *= sc;

    const Tab* wt = d_wtab + (b * S_) * W_ + w;   // stride W_ per step
    const Tab* ht = d_htab + (b * S_) * H_ + h;   // stride H_ per step

    __shared__ float sm[8][4][S_];   // [warp][pixel][step] = 4 KB

    const int rowPitch = W_ * (C_ / 4);   // float4 per image row
    const int bbase    = b * H_;

#pragma unroll 4
    for (int s = 0; s < S_; ++s) {
        Tab tw = wt[s * W_];
        Tab th = ht[s * H_];

        int r0 = (bbase + th.i0) * rowPitch;
        int r1 = (bbase + th.i1) * rowPitch;
        int c0 = tw.i0 * (C_ / 4) + cg;
        int c1 = tw.i1 * (C_ / 4) + cg;

        float4 t00 = x4[r0 + c0];
        float4 t01 = x4[r0 + c1];
        float4 t10 = x4[r1 + c0];
        float4 t11 = x4[r1 + c1];

        float vx = th.w0 * (tw.w0 * t00.x + tw.w1 * t01.x)
                 + th.w1 * (tw.w0 * t10.x + tw.w1 * t11.x);
        float vy = th.w0 * (tw.w0 * t00.y + tw.w1 * t01.y)
                 + th.w1 * (tw.w0 * t10.y + tw.w1 * t11.y);
        float vz = th.w0 * (tw.w0 * t00.z + tw.w1 * t01.z)
                 + th.w1 * (tw.w0 * t10.z + tw.w1 * t11.z);
        float vw = th.w0 * (tw.w0 * t00.w + tw.w1 * t01.w)
                 + th.w1 * (tw.w0 * t10.w + tw.w1 * t11.w);

        float partial = vx * yv.x + vy * yv.y + vz * yv.z + vw * yv.w;

        // reduce over the 8 channel lanes of this pixel
        partial += __shfl_xor_sync(0xffffffffu, partial, 1);
        partial += __shfl_xor_sync(0xffffffffu, partial, 2);
        partial += __shfl_xor_sync(0xffffffffu, partial, 4);

        if (cg == 0) sm[wi][sub][s] = partial;
    }

    __syncwarp();

    // Coalesced store: each thread writes 4 consecutive steps of its pixel.
    float4 o;
    o.x = sm[wi][sub][cg * 4 + 0];
    o.y = sm[wi][sub][cg * 4 + 1];
    o.z = sm[wi][sub][cg * 4 + 2];
    o.w = sm[wi][sub][cg * 4 + 3];
    out4[p * (S_ / 4) + cg] = o;
}

// ---------------------------------------------------------------------------
extern "C" void kernel_launch(void* const* d_in, const int* in_sizes, int n_in,
                              void* d_out, int out_size)
{
    (void)in_sizes; (void)n_in; (void)out_size;
    const float* x      = (const float*)d_in[0];
    const float* y      = (const float*)d_in[1];
    const float* origin = (const float*)d_in[2];
    const float* focal  = (const float*)d_in[3];
    const float* T12    = (const float*)d_in[4];

    int tabThreads = B_ * S_ * (W_ + H_);
    build_tables<<<(tabThreads + 255) / 256, 256>>>(origin, focal, T12);

    int nBlocks = (W_ / 8) * (H_ / 4) * B_;   // 15360
    corr_kernel<<<nBlocks, 256>>>((const float4*)x, (const float4*)y, (float4*)d_out);
}

// round 2
// speedup vs baseline: 1.5124x; 1.5124x over previous
#include <cuda_runtime.h>
#include <cuda_fp16.h>

// Problem constants
#define B_ 4
#define H_ 192
#define W_ 640
#define C_ 32
#define S_ 32

#define Wp_   (W_ + 2)                 // padded width (one extra pixel + shift room)
#define ROWB  (Wp_ * 64)               // bytes per row in fp16 scratch (64B/pixel)
#define COPYB (B_ * H_ * ROWB)         // bytes per parity copy

// ---------------------------------------------------------------------------
// Scratch: two parity-shifted fp16 copies of x.
//   copy0[wp] = x[wp]       (wp < W_, else 0)
//   copy1[wp] = x[wp - 1]   (1 <= wp <= W_, else 0)
// For base column ib:
//   ib even -> copy0, region starts at byte ib*64       (128B aligned)
//   ib odd  -> copy1, region starts at byte (ib+1)*64   (128B aligned)
// Either way the 128B region holds [ x[ib] | x[ib+1] ].
// ---------------------------------------------------------------------------
#define XS_CHUNKS (2 * B_ * H_ * Wp_ * 4)   // 16B chunks total = 3,944,448 (63.1 MB)
__device__ uint4 d_xs[XS_CHUNKS];

struct __align__(16) WTab { int off; float wa, wb; int pad; };
struct __align__(16) HTab { int r0, r1; float h0, h1; };

__device__ WTab d_wt[B_ * S_ * W_];
__device__ HTab d_ht[B_ * S_ * H_];

// ---------------------------------------------------------------------------
// Build per-(b,s,w) and per-(b,s,h) tables. Matches reference math in fp32.
// ---------------------------------------------------------------------------
__global__ void build_tables(const float* __restrict__ origin,
                             const float* __restrict__ focal,
                             const float* __restrict__ T12)
{
    int idx = blockIdx.x * blockDim.x + threadIdx.x;
    const int totalW = B_ * S_ * W_;
    const int totalH = B_ * S_ * H_;
    if (idx >= totalW + totalH) return;

    bool isW = idx < totalW;
    int rem  = isW ? idx : idx - totalW;
    int N    = isW ? W_ : H_;
    int pos  = rem % N;
    int s    = (rem / N) % S_;
    int b    = rem / (N * S_);

    float tz = T12[b * 3 + 2];
    float d  = (float)s;
    float D  = (s == 0) ? 0.0f : 1.0f / (1.0f / d + tz);
    float alpha = 1.0f - D * tz;

    float off;
    if (isW) off = D * tz * origin[b * 2 + 0] + D * focal[b * 2 + 0] * T12[b * 3 + 0];
    else     off = D * tz * origin[b * 2 + 1] + D * focal[b * 2 + 1] * T12[b * 3 + 1];

    float sp = alpha * (float)pos + off;
    float f0 = floorf(sp);
    float fr = sp - f0;
    int i0 = (int)f0;
    int i1 = i0 + 1;

    float w0 = (i0 >= 0 && i0 < N) ? (1.0f - fr) : 0.0f;
    float w1 = (i1 >= 0 && i1 < N) ? fr          : 0.0f;

    if (isW) {
        int ib; float wa, wb;
        if (i0 >= 0 && i0 < N)      { ib = i0; wa = w0; wb = w1; }
        else if (i0 == -1)          { ib = 0;  wa = w1; wb = 0.0f; }   // only i1=0 in range
        else                        { ib = min(max(i0, 0), N - 1); wa = 0.0f; wb = 0.0f; }
        WTab t;
        t.off = (ib & 1) ? (COPYB + (ib + 1) * 64) : (ib * 64);
        t.wa  = wa;
        t.wb  = wb;
        t.pad = 0;
        d_wt[(b * S_ + s) * W_ + pos] = t;
    } else {
        HTab t;
        int r0 = min(max(i0, 0), N - 1);
        int r1 = min(max(i1, 0), N - 1);
        t.r0 = (b * H_ + r0) * ROWB;
        t.r1 = (b * H_ + r1) * ROWB;
        t.h0 = w0;
        t.h1 = w1;
        d_ht[(b * S_ + s) * H_ + pos] = t;
    }
}

// ---------------------------------------------------------------------------
// Convert x (fp32, [B,H,W,32]) into the two parity-shifted fp16 copies.
// One thread = one 16B chunk (8 halfs = 8 channels). Stores fully coalesced.
// ---------------------------------------------------------------------------
__global__ void convert_x(const float4* __restrict__ x4)
{
    int t = blockIdx.x * blockDim.x + threadIdx.x;
    if (t >= XS_CHUNKS) return;

    int c16  = t & 3;           // which 16B of the 64B pixel vector
    int rest = t >> 2;
    int wp   = rest % Wp_;  rest /= Wp_;
    int h    = rest % H_;   rest /= H_;
    int b    = rest % B_;
    int copy = rest / B_;

    int w = wp - copy;
    uint4 o = make_uint4(0u, 0u, 0u, 0u);
    if (w >= 0 && w < W_) {
        const float4* src = x4 + ((((b * H_ + h) * W_ + w) << 3) + (c16 << 1));
        float4 p = src[0];
        float4 q = src[1];
        __half2 a0 = __floats2half2_rn(p.x, p.y);
        __half2 a1 = __floats2half2_rn(p.z, p.w);
        __half2 a2 = __floats2half2_rn(q.x, q.y);
        __half2 a3 = __floats2half2_rn(q.z, q.w);
        o.x = *(unsigned int*)&a0;
        o.y = *(unsigned int*)&a1;
        o.z = *(unsigned int*)&a2;
        o.w = *(unsigned int*)&a3;
    }
    d_xs[t] = o;
}

// ---------------------------------------------------------------------------
// Main kernel. Block = 256 threads = 8 warps = 8(w) x 4(h) pixel tile.
// Warp = 4 pixels (one h, 4 w). Lane: sub = lane>>3 (pixel), cg = lane&7:
//   cg bit2   -> column (x[ib] vs x[ib+1], weight wa vs wb)
//   cg bits01 -> channel group of 8
// Per step per pixel: 2 LDG.128 (one aligned 128B line per row, fully used).
// ---------------------------------------------------------------------------
__global__ __launch_bounds__(256, 5) void corr_kernel(
    const float4* __restrict__ y4,
    float4* __restrict__ out4)
{
    const int tid  = threadIdx.x;
    const int wi   = tid >> 5;
    const int lane = tid & 31;
    const int sub  = lane >> 3;
    const int cg   = lane & 7;

    int bx  = blockIdx.x;
    int twi = bx % (W_ / 8);
    int thi = (bx / (W_ / 8)) % (H_ / 4);
    int b   = bx / ((W_ / 8) * (H_ / 4));

    const int wl = (wi & 1) * 4 + sub;        // local w in [0,8)
    const int hl = wi >> 1;                   // local h in [0,4)
    int w = twi * 8 + wl;
    int h = thi * 4 + hl;
    int p = (b * H_ + h) * W_ + w;

    __shared__ uint4 swt[S_][8];
    __shared__ uint4 sht[S_][4];
    __shared__ float sm[8][4][S_];

    // Preload tables for this tile (all 32 steps)
    {
        int s = tid >> 3, e = tid & 7;                    // 256 = 32*8
        swt[s][e] = *(const uint4*)&d_wt[(b * S_ + s) * W_ + twi * 8 + e];
        if (tid < 128) {
            int s2 = tid >> 2, e2 = tid & 3;
            sht[s2][e2] = *(const uint4*)&d_ht[(b * S_ + s2) * H_ + thi * 4 + e2];
        }
    }

    // y channels for this lane's group, pre-scaled by 1/C
    float yv[8];
    {
        const float4* yp = y4 + (p << 3) + ((cg & 3) << 1);
        float4 a = yp[0], c = yp[1];
        const float sc = 1.0f / (float)C_;
        yv[0] = a.x * sc; yv[1] = a.y * sc; yv[2] = a.z * sc; yv[3] = a.w * sc;
        yv[4] = c.x * sc; yv[5] = c.y * sc; yv[6] = c.z * sc; yv[7] = c.w * sc;
    }

    __syncthreads();

    const char* xsb = (const char*)d_xs;
    const int laneByte = cg << 4;

#pragma unroll 2
    for (int s = 0; s < S_; ++s) {
        uint4 wt = *(const uint4*)&swt[s][wl];
        uint4 ht = *(const uint4*)&sht[s][hl];

        float wlw = (cg & 4) ? __uint_as_float(wt.z) : __uint_as_float(wt.y);
        float m0  = __uint_as_float(ht.z) * wlw;
        float m1  = __uint_as_float(ht.w) * wlw;

        const uint4* A4 = (const uint4*)(xsb + (ht.x + wt.x + laneByte));
        const uint4* B4 = (const uint4*)(xsb + (ht.y + wt.x + laneByte));
        uint4 A = *A4;
        uint4 Bv = *B4;

        // dot8(fp16 tap, fp32 y) in fp32
        float2 f0 = __half22float2(*(__half2*)&A.x);
        float2 f1 = __half22float2(*(__half2*)&A.y);
        float2 f2 = __half22float2(*(__half2*)&A.z);
        float2 f3 = __half22float2(*(__half2*)&A.w);
        float d0 = f0.x * yv[0] + f0.y * yv[1] + f1.x * yv[2] + f1.y * yv[3]
                 + f2.x * yv[4] + f2.y * yv[5] + f3.x * yv[6] + f3.y * yv[7];

        float2 g0 = __half22float2(*(__half2*)&Bv.x);
        float2 g1 = __half22float2(*(__half2*)&Bv.y);
        float2 g2 = __half22float2(*(__half2*)&Bv.z);
        float2 g3 = __half22float2(*(__half2*)&Bv.w);
        float d1 = g0.x * yv[0] + g0.y * yv[1] + g1.x * yv[2] + g1.y * yv[3]
                 + g2.x * yv[4] + g2.y * yv[5] + g3.x * yv[6] + g3.y * yv[7];

        float partial = m0 * d0 + m1 * d1;

        partial += __shfl_xor_sync(0xffffffffu, partial, 1);
        partial += __shfl_xor_sync(0xffffffffu, partial, 2);
        partial += __shfl_xor_sync(0xffffffffu, partial, 4);

        if (cg == 0) sm[wi][sub][s] = partial;
    }

    __syncwarp();

    float4 o;
    o.x = sm[wi][sub][cg * 4 + 0];
    o.y = sm[wi][sub][cg * 4 + 1];
    o.z = sm[wi][sub][cg * 4 + 2];
    o.w = sm[wi][sub][cg * 4 + 3];
    out4[(p << 3) + cg] = o;
}

// ---------------------------------------------------------------------------
extern "C" void kernel_launch(void* const* d_in, const int* in_sizes, int n_in,
                              void* d_out, int out_size)
{
    (void)in_sizes; (void)n_in; (void)out_size;
    const float* x      = (const float*)d_in[0];
    const float* y      = (const float*)d_in[1];
    const float* origin = (const float*)d_in[2];
    const float* focal  = (const float*)d_in[3];
    const float* T12    = (const float*)d_in[4];

    int tabThreads = B_ * S_ * (W_ + H_);
    build_tables<<<(tabThreads + 255) / 256, 256>>>(origin, focal, T12);

    convert_x<<<(XS_CHUNKS + 255) / 256, 256>>>((const float4*)x);

    int nBlocks = (W_ / 8) * (H_ / 4) * B_;   // 15360
    corr_kernel<<<nBlocks, 256>>>((const float4*)y, (float4*)d_out);
}

// round 3
// speedup vs baseline: 1.9125x; 1.2646x over previous
#include <cuda_runtime.h>
#include <cuda_fp16.h>

// Problem constants
#define B_ 4
#define H_ 192
#define W_ 640
#define C_ 32
#define S_ 32

#define Wp_   (W_ + 2)                 // padded width
#define ROWB  (Wp_ * 64)               // bytes per row in fp16 scratch (64B/pixel)
#define COPYB (B_ * H_ * ROWB)         // bytes per parity copy

// Two parity-shifted fp16 copies of x (see R2 comments): for base column ib,
// a single aligned 128B region holds [ x[ib] | x[ib+1] ].
#define XS_CHUNKS (2 * B_ * H_ * Wp_ * 4)
__device__ uint4 d_xs[XS_CHUNKS];

struct __align__(16) WTab { int off; float wa, wb; int pad; };
struct __align__(16) HTab { int r0, r1; float h0, h1; };

__device__ WTab d_wt[B_ * S_ * W_];
__device__ HTab d_ht[B_ * S_ * H_];

// ---------------------------------------------------------------------------
__global__ void build_tables(const float* __restrict__ origin,
                             const float* __restrict__ focal,
                             const float* __restrict__ T12)
{
    int idx = blockIdx.x * blockDim.x + threadIdx.x;
    const int totalW = B_ * S_ * W_;
    const int totalH = B_ * S_ * H_;
    if (idx >= totalW + totalH) return;

    bool isW = idx < totalW;
    int rem  = isW ? idx : idx - totalW;
    int N    = isW ? W_ : H_;
    int pos  = rem % N;
    int s    = (rem / N) % S_;
    int b    = rem / (N * S_);

    float tz = T12[b * 3 + 2];
    float d  = (float)s;
    float D  = (s == 0) ? 0.0f : 1.0f / (1.0f / d + tz);
    float alpha = 1.0f - D * tz;

    float off;
    if (isW) off = D * tz * origin[b * 2 + 0] + D * focal[b * 2 + 0] * T12[b * 3 + 0];
    else     off = D * tz * origin[b * 2 + 1] + D * focal[b * 2 + 1] * T12[b * 3 + 1];

    float sp = alpha * (float)pos + off;
    float f0 = floorf(sp);
    float fr = sp - f0;
    int i0 = (int)f0;
    int i1 = i0 + 1;

    float w0 = (i0 >= 0 && i0 < N) ? (1.0f - fr) : 0.0f;
    float w1 = (i1 >= 0 && i1 < N) ? fr          : 0.0f;

    if (isW) {
        int ib; float wa, wb;
        if (i0 >= 0 && i0 < N)      { ib = i0; wa = w0; wb = w1; }
        else if (i0 == -1)          { ib = 0;  wa = w1; wb = 0.0f; }
        else                        { ib = min(max(i0, 0), N - 1); wa = 0.0f; wb = 0.0f; }
        WTab t;
        t.off = (ib & 1) ? (COPYB + (ib + 1) * 64) : (ib * 64);
        t.wa  = wa;
        t.wb  = wb;
        t.pad = 0;
        d_wt[(b * S_ + s) * W_ + pos] = t;
    } else {
        HTab t;
        int r0 = min(max(i0, 0), N - 1);
        int r1 = min(max(i1, 0), N - 1);
        t.r0 = (b * H_ + r0) * ROWB;
        t.r1 = (b * H_ + r1) * ROWB;
        t.h0 = w0;
        t.h1 = w1;
        d_ht[(b * S_ + s) * H_ + pos] = t;
    }
}

// ---------------------------------------------------------------------------
__global__ void convert_x(const float4* __restrict__ x4)
{
    int t = blockIdx.x * blockDim.x + threadIdx.x;
    if (t >= XS_CHUNKS) return;

    int c16  = t & 3;
    int rest = t >> 2;
    int wp   = rest % Wp_;  rest /= Wp_;
    int h    = rest % H_;   rest /= H_;
    int b    = rest % B_;
    int copy = rest / B_;

    int w = wp - copy;
    uint4 o = make_uint4(0u, 0u, 0u, 0u);
    if (w >= 0 && w < W_) {
        const float4* src = x4 + ((((b * H_ + h) * W_ + w) << 3) + (c16 << 1));
        float4 p = src[0];
        float4 q = src[1];
        __half2 a0 = __floats2half2_rn(p.x, p.y);
        __half2 a1 = __floats2half2_rn(p.z, p.w);
        __half2 a2 = __floats2half2_rn(q.x, q.y);
        __half2 a3 = __floats2half2_rn(q.z, q.w);
        o.x = *(unsigned int*)&a0;
        o.y = *(unsigned int*)&a1;
        o.z = *(unsigned int*)&a2;
        o.w = *(unsigned int*)&a3;
    }
    d_xs[t] = o;
}

// ---------------------------------------------------------------------------
// Packed f32x2 helpers (sm_103a FFMA2)
// ---------------------------------------------------------------------------
__device__ __forceinline__ unsigned long long fma2_(unsigned long long a,
                                                    unsigned long long b,
                                                    unsigned long long c)
{
    unsigned long long d;
    asm("fma.rn.f32x2 %0, %1, %2, %3;" : "=l"(d) : "l"(a), "l"(b), "l"(c));
    return d;
}
__device__ __forceinline__ unsigned long long mul2_(unsigned long long a,
                                                    unsigned long long b)
{
    unsigned long long d;
    asm("mul.rn.f32x2 %0, %1, %2;" : "=l"(d) : "l"(a), "l"(b));
    return d;
}
__device__ __forceinline__ unsigned long long pack2_(float lo, float hi)
{
    unsigned long long d;
    asm("mov.b64 %0, {%1, %2};" : "=l"(d) : "f"(lo), "f"(hi));
    return d;
}
__device__ __forceinline__ __half2 u2h2_(unsigned int u)
{
    __half2 h; *(unsigned int*)&h = u; return h;
}

// ---------------------------------------------------------------------------
// Main kernel. Layout identical to R2 (warp = 4 pixels x 8 chan-lanes), but:
//  - interp in packed fp16 HFMA2 (weights folded into half2)
//  - channel dot in packed f32x2 FFMA2 with fp32 y (accumulation fp32)
//  - 4 steps per group, butterfly 4-value reduce (4 shuffles, not 12),
//    direct predicated STG (no smem staging)
// ---------------------------------------------------------------------------
__global__ __launch_bounds__(256, 4) void corr_kernel(
    const float4* __restrict__ y4,
    float* __restrict__ out)
{
    const int tid  = threadIdx.x;
    const int wi   = tid >> 5;
    const int lane = tid & 31;
    const int sub  = lane >> 3;
    const int cg   = lane & 7;

    int bx  = blockIdx.x;
    int twi = bx % (W_ / 8);
    int thi = (bx / (W_ / 8)) % (H_ / 4);
    int b   = bx / ((W_ / 8) * (H_ / 4));

    const int wl = (wi & 1) * 4 + sub;
    const int hl = wi >> 1;
    int w = twi * 8 + wl;
    int h = thi * 4 + hl;
    int p = (b * H_ + h) * W_ + w;

    __shared__ uint4 swt[S_][8];
    __shared__ uint4 sht[S_][4];

    {
        int s = tid >> 3, e = tid & 7;
        swt[s][e] = *(const uint4*)&d_wt[(b * S_ + s) * W_ + twi * 8 + e];
        if (tid < 128) {
            int s2 = tid >> 2, e2 = tid & 3;
            sht[s2][e2] = *(const uint4*)&d_ht[(b * S_ + s2) * H_ + thi * 4 + e2];
        }
    }

    // y channels for this lane's group (fp32), pre-scaled by 1/C, packed f32x2
    unsigned long long z[4];
    {
        const float4* yp = y4 + (p << 3) + ((cg & 3) << 1);
        float4 a = yp[0], c = yp[1];
        const float sc = 1.0f / (float)C_;
        z[0] = pack2_(a.x * sc, a.y * sc);
        z[1] = pack2_(a.z * sc, a.w * sc);
        z[2] = pack2_(c.x * sc, c.y * sc);
        z[3] = pack2_(c.z * sc, c.w * sc);
    }

    __syncthreads();

    const char* xsb = (const char*)d_xs;
    const int laneByte = cg << 4;
    const bool hiCol = (cg & 4) != 0;
    float* outp = out + p * S_;

#pragma unroll 2
    for (int g = 0; g < S_ / 4; ++g) {
        float pr[4];
#pragma unroll
        for (int i = 0; i < 4; ++i) {
            int s = g * 4 + i;
            uint4 wt = swt[s][wl];
            uint4 ht = sht[s][hl];

            float wlw = hiCol ? __uint_as_float(wt.z) : __uint_as_float(wt.y);
            float m0  = __uint_as_float(ht.z) * wlw;
            float m1  = __uint_as_float(ht.w) * wlw;
            __half2 m0h = __float2half2_rn(m0);
            __half2 m1h = __float2half2_rn(m1);

            const uint4 A  = *(const uint4*)(xsb + (ht.x + wt.x + laneByte));
            const uint4 Bv = *(const uint4*)(xsb + (ht.y + wt.x + laneByte));

            __half2 v0 = __hfma2(m0h, u2h2_(A.x), __hmul2(m1h, u2h2_(Bv.x)));
            __half2 v1 = __hfma2(m0h, u2h2_(A.y), __hmul2(m1h, u2h2_(Bv.y)));
            __half2 v2 = __hfma2(m0h, u2h2_(A.z), __hmul2(m1h, u2h2_(Bv.z)));
            __half2 v3 = __hfma2(m0h, u2h2_(A.w), __hmul2(m1h, u2h2_(Bv.w)));

            float2 f0 = __half22float2(v0);
            float2 f1 = __half22float2(v1);
            float2 f2 = __half22float2(v2);
            float2 f3 = __half22float2(v3);

            unsigned long long acc = mul2_(pack2_(f0.x, f0.y), z[0]);
            acc = fma2_(pack2_(f1.x, f1.y), z[1], acc);
            acc = fma2_(pack2_(f2.x, f2.y), z[2], acc);
            acc = fma2_(pack2_(f3.x, f3.y), z[3], acc);

            float2 af = *(float2*)&acc;
            pr[i] = af.x + af.y;
        }

        // Butterfly: reduce 4 values over the 8 lanes of this pixel.
        // Stage 1 (xor 4): low half keeps (s0,s1), high half keeps (s2,s3).
        float u = hiCol ? pr[0] : pr[2];
        float v = hiCol ? pr[1] : pr[3];
        u = __shfl_xor_sync(0xffffffffu, u, 4);
        v = __shfl_xor_sync(0xffffffffu, v, 4);
        float a = hiCol ? (pr[2] + u) : (pr[0] + u);
        float bb = hiCol ? (pr[3] + v) : (pr[1] + v);
        // Stage 2 (xor 2): bit1==0 keeps a, bit1==1 keeps bb.
        bool hi2 = (cg & 2) != 0;
        float t = hi2 ? a : bb;
        t = __shfl_xor_sync(0xffffffffu, t, 2);
        float r = (hi2 ? bb : a) + t;
        // Stage 3 (xor 1): full sum; lanes 2k & 2k+1 both hold s_k.
        r += __shfl_xor_sync(0xffffffffu, r, 1);

        if ((cg & 1) == 0) outp[g * 4 + (cg >> 1)] = r;
    }
}

// ---------------------------------------------------------------------------
extern "C" void kernel_launch(void* const* d_in, const int* in_sizes, int n_in,
                              void* d_out, int out_size)
{
    (void)in_sizes; (void)n_in; (void)out_size;
    const float* x      = (const float*)d_in[0];
    const float* y      = (const float*)d_in[1];
    const float* origin = (const float*)d_in[2];
    const float* focal  = (const float*)d_in[3];
    const float* T12    = (const float*)d_in[4];

    int tabThreads = B_ * S_ * (W_ + H_);
    build_tables<<<(tabThreads + 255) / 256, 256>>>(origin, focal, T12);

    convert_x<<<(XS_CHUNKS + 255) / 256, 256>>>((const float4*)x);

    int nBlocks = (W_ / 8) * (H_ / 4) * B_;   // 15360
    corr_kernel<<<nBlocks, 256>>>((const float4*)y, (float*)d_out);
}

// round 4
// speedup vs baseline: 2.0508x; 1.0723x over previous
#include <cuda_runtime.h>
#include <cuda_fp16.h>

// Problem constants
#define B_ 4
#define H_ 192
#define W_ 640
#define C_ 32
#define S_ 32

#define Wp_   (W_ + 2)                 // padded width
#define ROWB  (Wp_ * 64)               // bytes per row in fp16 scratch (64B/pixel)
#define COPYB (B_ * H_ * ROWB)         // bytes per parity copy

// Two parity-shifted fp16 copies of x: for base column ib, one aligned 128B
// region holds [ x[ib] | x[ib+1] ] (copy0 for even ib, copy1 for odd ib).
#define COPY_CHUNKS (B_ * H_ * Wp_ * 4)
#define XS_CHUNKS   (2 * COPY_CHUNKS)
__device__ uint4 d_xs[XS_CHUNKS];

// w-table: per (b,s,col,w): { byte-offset (incl. parity-copy base), weight fp32 }
struct __align__(8) WTab2 { int off; float w; };
__device__ WTab2 d_wt2[B_ * S_ * 2 * W_];
// h-table: per (b,s,h): { row0 byte base, row1 byte base, h0 fp32, h1 fp32 }
struct __align__(16) HTab { int r0, r1; float h0, h1; };
__device__ HTab d_ht[B_ * S_ * H_];

#define TAB_THREADS (B_ * S_ * (W_ + H_))
#define TAB_BLOCKS  ((TAB_THREADS + 255) / 256)
#define CONV_THREADS (B_ * H_ * Wp_ * 4)
#define CONV_BLOCKS  ((CONV_THREADS + 255) / 256)

// ---------------------------------------------------------------------------
// Fused prep kernel: table build + fp16 conversion (x read ONCE, both copies
// written from the same value: copy1[wp+1] == copy0[wp]).
// ---------------------------------------------------------------------------
__global__ void prep_kernel(const float4* __restrict__ x4,
                            const float* __restrict__ origin,
                            const float* __restrict__ focal,
                            const float* __restrict__ T12)
{
    if (blockIdx.x < TAB_BLOCKS) {
        int idx = blockIdx.x * blockDim.x + threadIdx.x;
        const int totalW = B_ * S_ * W_;
        const int totalH = B_ * S_ * H_;
        if (idx >= totalW + totalH) return;

        bool isW = idx < totalW;
        int rem  = isW ? idx : idx - totalW;
        int N    = isW ? W_ : H_;
        int pos  = rem % N;
        int s    = (rem / N) % S_;
        int b    = rem / (N * S_);

        float tz = T12[b * 3 + 2];
        float d  = (float)s;
        float D  = (s == 0) ? 0.0f : 1.0f / (1.0f / d + tz);
        float alpha = 1.0f - D * tz;

        float off;
        if (isW) off = D * tz * origin[b * 2 + 0] + D * focal[b * 2 + 0] * T12[b * 3 + 0];
        else     off = D * tz * origin[b * 2 + 1] + D * focal[b * 2 + 1] * T12[b * 3 + 1];

        float sp = alpha * (float)pos + off;
        float f0 = floorf(sp);
        float fr = sp - f0;
        int i0 = (int)f0;
        int i1 = i0 + 1;

        float w0 = (i0 >= 0 && i0 < N) ? (1.0f - fr) : 0.0f;
        float w1 = (i1 >= 0 && i1 < N) ? fr          : 0.0f;

        if (isW) {
            int ib; float wa, wb;
            if (i0 >= 0 && i0 < N)      { ib = i0; wa = w0; wb = w1; }
            else if (i0 == -1)          { ib = 0;  wa = w1; wb = 0.0f; }
            else                        { ib = min(max(i0, 0), N - 1); wa = 0.0f; wb = 0.0f; }
            int byteOff = (ib & 1) ? (COPYB + (ib + 1) * 64) : (ib * 64);
            int base = (b * S_ + s) * 2 * W_ + pos;
            WTab2 t0; t0.off = byteOff; t0.w = wa;
            WTab2 t1; t1.off = byteOff; t1.w = wb;
            d_wt2[base]      = t0;
            d_wt2[base + W_] = t1;
        } else {
            HTab t;
            int r0 = min(max(i0, 0), N - 1);
            int r1 = min(max(i1, 0), N - 1);
            t.r0 = (b * H_ + r0) * ROWB;
            t.r1 = (b * H_ + r1) * ROWB;
            t.h0 = w0;
            t.h1 = w1;
            d_ht[(b * S_ + s) * H_ + pos] = t;
        }
        return;
    }

    // --- conversion part ---
    int t = (blockIdx.x - TAB_BLOCKS) * blockDim.x + threadIdx.x;
    if (t >= CONV_THREADS) return;

    int c16  = t & 3;
    int rest = t >> 2;
    int wp   = rest % Wp_;  rest /= Wp_;
    int h    = rest % H_;
    int b    = rest / H_;

    uint4 o = make_uint4(0u, 0u, 0u, 0u);
    if (wp < W_) {
        const float4* src = x4 + ((((b * H_ + h) * W_ + wp) << 3) + (c16 << 1));
        float4 p = src[0];
        float4 q = src[1];
        __half2 a0 = __floats2half2_rn(p.x, p.y);
        __half2 a1 = __floats2half2_rn(p.z, p.w);
        __half2 a2 = __floats2half2_rn(q.x, q.y);
        __half2 a3 = __floats2half2_rn(q.z, q.w);
        o.x = *(unsigned int*)&a0;
        o.y = *(unsigned int*)&a1;
        o.z = *(unsigned int*)&a2;
        o.w = *(unsigned int*)&a3;
    }

    int rowChunk = (b * H_ + h) * Wp_ * 4;
    d_xs[rowChunk + wp * 4 + c16] = o;                                 // copy0[wp]
    if (wp + 1 < Wp_)
        d_xs[COPY_CHUNKS + rowChunk + (wp + 1) * 4 + c16] = o;          // copy1[wp+1] = x[wp]
    if (wp == 0)
        d_xs[COPY_CHUNKS + rowChunk + c16] = make_uint4(0u, 0u, 0u, 0u); // copy1[0] pad
}

// ---------------------------------------------------------------------------
// Packed f32x2 helpers (sm_103a FFMA2)
// ---------------------------------------------------------------------------
__device__ __forceinline__ unsigned long long fma2_(unsigned long long a,
                                                    unsigned long long b,
                                                    unsigned long long c)
{
    unsigned long long d;
    asm("fma.rn.f32x2 %0, %1, %2, %3;" : "=l"(d) : "l"(a), "l"(b), "l"(c));
    return d;
}
__device__ __forceinline__ unsigned long long mul2_(unsigned long long a,
                                                    unsigned long long b)
{
    unsigned long long d;
    asm("mul.rn.f32x2 %0, %1, %2;" : "=l"(d) : "l"(a), "l"(b));
    return d;
}
__device__ __forceinline__ unsigned long long pack2_(float lo, float hi)
{
    unsigned long long d;
    asm("mov.b64 %0, {%1, %2};" : "=l"(d) : "f"(lo), "f"(hi));
    return d;
}
__device__ __forceinline__ __half2 u2h2_(unsigned int u)
{
    __half2 h; *(unsigned int*)&h = u; return h;
}

// ---------------------------------------------------------------------------
// Main kernel. Warp = 4 pixels x 8 chan-lanes (cg bit2 = tap column,
// cg bits01 = channel group). Per pixel-step: 2 LDG.128 (one aligned 128B
// line per tap row, fully utilized — byte floor). Weights: m0/m1 in fp32,
// one pack-to-half2, PRMT broadcasts (alu pipe). Dot in packed f32x2.
// ---------------------------------------------------------------------------
__global__ __launch_bounds__(256, 5) void corr_kernel(
    const float4* __restrict__ y4,
    float* __restrict__ out)
{
    const int tid  = threadIdx.x;
    const int wi   = tid >> 5;
    const int lane = tid & 31;
    const int sub  = lane >> 3;
    const int cg   = lane & 7;
    const int hiCol = (cg >> 2) & 1;

    int bx  = blockIdx.x;
    int twi = bx % (W_ / 8);
    int thi = (bx / (W_ / 8)) % (H_ / 4);
    int b   = bx / ((W_ / 8) * (H_ / 4));

    const int wl = (wi & 1) * 4 + sub;
    const int hl = wi >> 1;
    int w = twi * 8 + wl;
    int h = thi * 4 + hl;
    int p = (b * H_ + h) * W_ + w;

    __shared__ uint2 swt[S_][2][8];   // [step][col][wl] = {off, w fp32}  (4KB)
    __shared__ uint4 sht[S_][4];      // [step][hl]      = {r0, r1, h0, h1} (2KB)

    {
        // 512 WTab2 entries, 2 per thread; global layout [b][s][col][w]
        int s = tid >> 3, e = tid & 7;
        int gbase = (b * S_ + s) * 2 * W_ + twi * 8 + e;
        swt[s][0][e] = *(const uint2*)&d_wt2[gbase];
        swt[s][1][e] = *(const uint2*)&d_wt2[gbase + W_];
        if (tid < 128) {
            int s2 = tid >> 2, e2 = tid & 3;
            sht[s2][e2] = *(const uint4*)&d_ht[(b * S_ + s2) * H_ + thi * 4 + e2];
        }
    }

    // y channels for this lane's group (fp32), pre-scaled by 1/C, packed f32x2
    unsigned long long z[4];
    {
        const float4* yp = y4 + (p << 3) + ((cg & 3) << 1);
        float4 a = yp[0], c = yp[1];
        const float sc = 1.0f / (float)C_;
        z[0] = pack2_(a.x * sc, a.y * sc);
        z[1] = pack2_(a.z * sc, a.w * sc);
        z[2] = pack2_(c.x * sc, c.y * sc);
        z[3] = pack2_(c.z * sc, c.w * sc);
    }

    __syncthreads();

    const char* xsb = (const char*)d_xs;
    const int laneByte = cg << 4;
    float* outp = out + p * S_;

#pragma unroll 1
    for (int g = 0; g < S_ / 4; ++g) {
        float pr[4];
#pragma unroll
        for (int i = 0; i < 4; ++i) {
            int s = g * 4 + i;
            uint2 wt = swt[s][hiCol][wl];
            uint4 ht = sht[s][hl];

            float wlw = __uint_as_float(wt.y);
            float m0  = __uint_as_float(ht.z) * wlw;
            float m1  = __uint_as_float(ht.w) * wlw;
            __half2 m01 = __floats2half2_rn(m0, m1);
            unsigned m01u = *(unsigned*)&m01;
            __half2 m0h = u2h2_(__byte_perm(m01u, 0, 0x1010));
            __half2 m1h = u2h2_(__byte_perm(m01u, 0, 0x3232));

            const uint4 A  = *(const uint4*)(xsb + (ht.x + wt.x + laneByte));
            const uint4 Bv = *(const uint4*)(xsb + (ht.y + wt.x + laneByte));

            __half2 v0 = __hfma2(m0h, u2h2_(A.x), __hmul2(m1h, u2h2_(Bv.x)));
            __half2 v1 = __hfma2(m0h, u2h2_(A.y), __hmul2(m1h, u2h2_(Bv.y)));
            __half2 v2 = __hfma2(m0h, u2h2_(A.z), __hmul2(m1h, u2h2_(Bv.z)));
            __half2 v3 = __hfma2(m0h, u2h2_(A.w), __hmul2(m1h, u2h2_(Bv.w)));

            float2 f0 = __half22float2(v0);
            float2 f1 = __half22float2(v1);
            float2 f2 = __half22float2(v2);
            float2 f3 = __half22float2(v3);

            unsigned long long acc = mul2_(pack2_(f0.x, f0.y), z[0]);
            acc = fma2_(pack2_(f1.x, f1.y), z[1], acc);
            acc = fma2_(pack2_(f2.x, f2.y), z[2], acc);
            acc = fma2_(pack2_(f3.x, f3.y), z[3], acc);

            float2 af = *(float2*)&acc;
            pr[i] = af.x + af.y;
        }

        // Butterfly: reduce 4 values over the 8 lanes of this pixel.
        float u = hiCol ? pr[0] : pr[2];
        float v = hiCol ? pr[1] : pr[3];
        u = __shfl_xor_sync(0xffffffffu, u, 4);
        v = __shfl_xor_sync(0xffffffffu, v, 4);
        float a  = hiCol ? (pr[2] + u) : (pr[0] + u);
        float bb = hiCol ? (pr[3] + v) : (pr[1] + v);
        bool hi2 = (cg & 2) != 0;
        float t = hi2 ? a : bb;
        t = __shfl_xor_sync(0xffffffffu, t, 2);
        float r = (hi2 ? bb : a) + t;
        r += __shfl_xor_sync(0xffffffffu, r, 1);

        if ((cg & 1) == 0) outp[g * 4 + (cg >> 1)] = r;
    }
}

// ---------------------------------------------------------------------------
extern "C" void kernel_launch(void* const* d_in, const int* in_sizes, int n_in,
                              void* d_out, int out_size)
{
    (void)in_sizes; (void)n_in; (void)out_size;
    const float* x      = (const float*)d_in[0];
    const float* y      = (const float*)d_in[1];
    const float* origin = (const float*)d_in[2];
    const float* focal  = (const float*)d_in[3];
    const float* T12    = (const float*)d_in[4];

    prep_kernel<<<TAB_BLOCKS + CONV_BLOCKS, 256>>>((const float4*)x, origin, focal, T12);

    int nBlocks = (W_ / 8) * (H_ / 4) * B_;   // 15360
    corr_kernel<<<nBlocks, 256>>>((const float4*)y, (float*)d_out);
}